// round 10
// baseline (speedup 1.0000x reference)
#include <cuda_runtime.h>
#include <cuda_fp16.h>
#include <cstdint>
#include <math.h>

#define B_  8192
#define H_  512
#define G3_ 1536
#define V_  2048
#define T_  24

// residual scale 2^11
#define RSC   2048.0f
#define RSCI  4.8828125e-4f

// ---------------------------------------------------------------------------
// Scratch (device globals: allocation-free)
// ---------------------------------------------------------------------------
__device__ float g_h[B_ * H_];
__device__ float g_gi[B_ * G3_];
__device__ float g_gh[B_ * G3_];
__device__ float g_logits[B_ * V_];

// scaled fp16x2 splits: X = X0 + X1 * 2^-11
__device__ __half g_IA0[B_ * H_],  g_IA1[B_ * H_];
__device__ __half g_HA0[B_ * H_],  g_HA1[B_ * H_];
__device__ __half g_Wih0[G3_ * H_], g_Wih1[G3_ * H_];
__device__ __half g_Whh0[G3_ * H_], g_Whh1[G3_ * H_];
__device__ __half g_Wo0[V_ * H_],   g_Wo1[V_ * H_];

// ---------------------------------------------------------------------------
// Threefry-2x32 (exact JAX replica)
// ---------------------------------------------------------------------------
__host__ __device__ __forceinline__ uint32_t rotl32(uint32_t v, int r) {
    return (v << r) | (v >> (32 - r));
}

__host__ __device__ __forceinline__ void tf2x32(uint32_t k0, uint32_t k1,
                                                uint32_t c0, uint32_t c1,
                                                uint32_t &o0, uint32_t &o1) {
    const uint32_t k2 = k0 ^ k1 ^ 0x1BD11BDAu;
    uint32_t a = c0, b = c1;
    a += k0; b += k1;
#define TFR(r) { a += b; b = rotl32(b, r); b ^= a; }
    TFR(13) TFR(15) TFR(26) TFR(6)
    a += k1; b += k2 + 1u;
    TFR(17) TFR(29) TFR(16) TFR(24)
    a += k2; b += k0 + 2u;
    TFR(13) TFR(15) TFR(26) TFR(6)
    a += k0; b += k1 + 3u;
    TFR(17) TFR(29) TFR(16) TFR(24)
    a += k1; b += k2 + 4u;
    TFR(13) TFR(15) TFR(26) TFR(6)
    a += k2; b += k0 + 5u;
#undef TFR
    o0 = a; o1 = b;
}

__device__ __forceinline__ float gumbelf(uint32_t bits) {
    float f = __uint_as_float((bits >> 9) | 0x3F800000u) - 1.0f;
    float u = fmaxf(1.17549435082228751e-38f, f);
    return -logf(-logf(u));
}

__device__ __forceinline__ float sigx(float v) {
    return 0.5f * tanhf(0.5f * v) + 0.5f;
}

// scaled fp16x2 split: x ≈ h0 + h1 * 2^-11
__device__ __forceinline__ void split2(float x, __half &h0, __half &h1) {
    h0 = __float2half_rn(x);
    float r = x - __half2float(h0);
    h1 = __float2half_rn(r * RSC);
}

// ---------------------------------------------------------------------------
// mma.sync / ldmatrix / cp.async primitives
// ---------------------------------------------------------------------------
__device__ __forceinline__ uint32_t smem_u32(const void* p) {
    uint32_t a;
    asm("{ .reg .u64 t; cvta.to.shared.u64 t, %1; cvt.u32.u64 %0, t; }"
        : "=r"(a) : "l"(p));
    return a;
}

__device__ __forceinline__ void ldsm4(uint32_t &r0, uint32_t &r1,
                                      uint32_t &r2, uint32_t &r3, uint32_t addr) {
    asm volatile("ldmatrix.sync.aligned.m8n8.x4.shared.b16 {%0,%1,%2,%3}, [%4];"
                 : "=r"(r0), "=r"(r1), "=r"(r2), "=r"(r3) : "r"(addr));
}

__device__ __forceinline__ void mma16816(float *d, const uint32_t *a,
                                         uint32_t b0, uint32_t b1) {
    asm volatile(
        "mma.sync.aligned.m16n8k16.row.col.f32.f16.f16.f32 "
        "{%0,%1,%2,%3},{%4,%5,%6,%7},{%8,%9},{%0,%1,%2,%3};"
        : "+f"(d[0]), "+f"(d[1]), "+f"(d[2]), "+f"(d[3])
        : "r"(a[0]), "r"(a[1]), "r"(a[2]), "r"(a[3]), "r"(b0), "r"(b1));
}

__device__ __forceinline__ void cp16(uint32_t saddr, const void *g) {
    asm volatile("cp.async.cg.shared.global [%0], [%1], 16;"
                 :: "r"(saddr), "l"(g));
}
#define CP_COMMIT() asm volatile("cp.async.commit_group;" ::: "memory")
#define CP_WAIT(n)  asm volatile("cp.async.wait_group %0;" :: "n"(n) : "memory")

struct GemmOps { const __half *a0, *a1, *b0, *b1;
                 const float *bias; float *c; };

// ---------------------------------------------------------------------------
// Standalone scaled-fp16x2 GEMM (128x128 CTA tile, 512 thr, 16 warps 4x4).
// Used for gi, logits, and the prologue gate pair.
// ---------------------------------------------------------------------------
#define TILE_B   8192
#define STAGE_B  (4 * TILE_B)
#define SMEM_TOT (2 * STAGE_B)

__global__ void __launch_bounds__(512)
gemm_f16x2(GemmOps op0, GemmOps op1, int N, int use2) {
    extern __shared__ char smem[];
    const uint32_t sb = smem_u32(smem);
    const int tid = threadIdx.x;
    const int wid = tid >> 5;
    const int lane = tid & 31;
    const int m0 = blockIdx.y << 7;
    const int n0 = blockIdx.x << 7;
    const int wm = wid >> 2;
    const int wn = wid & 3;

    const GemmOps &op = (use2 && blockIdx.z) ? op1 : op0;
    const __half *mats[4] = {
        op.a0 + (size_t)m0 * 512, op.a1 + (size_t)m0 * 512,
        op.b0 + (size_t)n0 * 512, op.b1 + (size_t)n0 * 512};

    auto issue = [&](int ch, int buf) {
        const uint32_t bbase = sb + (uint32_t)buf * STAGE_B;
#pragma unroll
        for (int s = 0; s < 4; ++s) {
            int seg = tid + s * 512;
            int m = seg >> 9;
            int w = seg & 511;
            int row = w >> 2;
            int u = w & 3;
            uint32_t bo = (uint32_t)(row << 6) + (uint32_t)(u << 4);
            uint32_t sw = bo ^ ((bo >> 3) & 0x30u);
            cp16(bbase + m * TILE_B + sw,
                 mats[m] + (size_t)row * 512 + (ch << 5) + (u << 3));
        }
        CP_COMMIT();
    };

    float hi[2][4][4], lo[2][4][4];
#pragma unroll
    for (int i = 0; i < 2; i++)
#pragma unroll
        for (int j = 0; j < 4; j++)
#pragma unroll
            for (int k = 0; k < 4; k++) { hi[i][j][k] = 0.0f; lo[i][j][k] = 0.0f; }

    issue(0, 0);

#pragma unroll 1
    for (int ch = 0; ch < 16; ++ch) {
        const int buf = ch & 1;
        if (ch < 15) { issue(ch + 1, buf ^ 1); CP_WAIT(1); }
        else         { CP_WAIT(0); }
        __syncthreads();

        const uint32_t stage = sb + (uint32_t)buf * STAGE_B;

#pragma unroll
        for (int ks = 0; ks < 2; ++ks) {
            const uint32_t kb = (uint32_t)(ks * 32) + (uint32_t)((lane >> 4) << 4);

            uint32_t bq[2][2][4];
#pragma unroll
            for (int sp = 0; sp < 2; ++sp) {
                const uint32_t Bt = stage + (2 + sp) * TILE_B;
#pragma unroll
                for (int nh = 0; nh < 2; ++nh) {
                    uint32_t row = (uint32_t)(wn * 32 + nh * 16 + (lane & 15));
                    uint32_t bo = (row << 6) + kb;
                    uint32_t sw = bo ^ ((bo >> 3) & 0x30u);
                    ldsm4(bq[sp][nh][0], bq[sp][nh][1], bq[sp][nh][2], bq[sp][nh][3],
                          Bt + sw);
                }
            }
            uint32_t af[2][2][4];
#pragma unroll
            for (int sp = 0; sp < 2; ++sp) {
                const uint32_t At = stage + sp * TILE_B;
#pragma unroll
                for (int mi = 0; mi < 2; ++mi) {
                    uint32_t row = (uint32_t)(wm * 32 + mi * 16 + (lane & 15));
                    uint32_t bo = (row << 6) + kb;
                    uint32_t sw = bo ^ ((bo >> 3) & 0x30u);
                    ldsm4(af[sp][mi][0], af[sp][mi][1], af[sp][mi][2], af[sp][mi][3],
                          At + sw);
                }
            }
#pragma unroll
            for (int mi = 0; mi < 2; ++mi)
#pragma unroll
                for (int ni = 0; ni < 4; ++ni) {
                    uint32_t b00 = bq[0][ni >> 1][ni & 1];
                    uint32_t b01 = bq[0][ni >> 1][(ni & 1) + 2];
                    uint32_t b10 = bq[1][ni >> 1][ni & 1];
                    uint32_t b11 = bq[1][ni >> 1][(ni & 1) + 2];
                    mma16816(hi[mi][ni], af[0][mi], b00, b01);
                    mma16816(lo[mi][ni], af[0][mi], b10, b11);
                    mma16816(lo[mi][ni], af[1][mi], b00, b01);
                }
        }
        __syncthreads();
    }

    const int tr = lane >> 2;
    const int tc = (lane & 3) << 1;
#pragma unroll
    for (int ni = 0; ni < 4; ++ni) {
        const int col = n0 + wn * 32 + ni * 8 + tc;
        const float bx = op.bias[col];
        const float by = op.bias[col + 1];
#pragma unroll
        for (int mi = 0; mi < 2; ++mi) {
            const int r0 = m0 + wm * 32 + mi * 16 + tr;
            float2 v0, v1;
            v0.x = fmaf(lo[mi][ni][0], RSCI, hi[mi][ni][0]) + bx;
            v0.y = fmaf(lo[mi][ni][1], RSCI, hi[mi][ni][1]) + by;
            v1.x = fmaf(lo[mi][ni][2], RSCI, hi[mi][ni][2]) + bx;
            v1.y = fmaf(lo[mi][ni][3], RSCI, hi[mi][ni][3]) + by;
            *(float2 *)(op.c + (size_t)r0 * N + col) = v0;
            *(float2 *)(op.c + (size_t)(r0 + 8) * N + col) = v1;
        }
    }
}

// ---------------------------------------------------------------------------
// Fused kernel: blocks [0, 8192) = sampling(t); blocks [8192, ...) = gh GEMM
// tiles for step t+1 (g_gh = HA @ Whh^T + b_hh). 256 threads per block.
// GEMM part: CTA tile 64x128 (M x N), 8 warps 2x4, warp tile 32x32.
// Both parts touch disjoint data; gh depends only on h'(t), not on sample.
// ---------------------------------------------------------------------------
#define FS_TILEA 4096                    // 64x32 fp16
#define FS_TILEB 8192                    // 128x32 fp16
#define FS_STAGE (2 * FS_TILEA + 2 * FS_TILEB)   // 24 KB
#define FS_SMEM  (2 * FS_STAGE)                  // 48 KB

__global__ void __launch_bounds__(256)
fused_sample_gh(const float *__restrict__ etab, uint32_t k0, uint32_t k1, int t,
                float *__restrict__ oSeq, float *__restrict__ oLp,
                float *__restrict__ oEnt,
                const float *__restrict__ logits, GemmOps gh) {
    extern __shared__ char smem[];
    const int tid = threadIdx.x;
    const int wid = tid >> 5;
    const int lane = tid & 31;

    if (blockIdx.x >= B_) {
        // ---------------- gh GEMM tile ----------------
        const uint32_t sb = smem_u32(smem);
        const int bid = blockIdx.x - B_;
        const int n0 = (bid % 12) << 7;          // 12 n-tiles of 128
        const int m0 = (bid / 12) << 6;          // 128 m-tiles of 64
        const int wm = wid >> 2;                 // 0..1
        const int wn = wid & 3;                  // 0..3

        const __half *A[2] = {gh.a0 + (size_t)m0 * 512, gh.a1 + (size_t)m0 * 512};
        const __half *Bm[2] = {gh.b0 + (size_t)n0 * 512, gh.b1 + (size_t)n0 * 512};

        auto issue = [&](int ch, int buf) {
            const uint32_t bbase = sb + (uint32_t)buf * FS_STAGE;
#pragma unroll
            for (int s = 0; s < 6; ++s) {
                int seg = tid + s * 256;             // 0..1535
                uint32_t dst; const __half *src;
                if (seg < 512) {
                    int sp = seg >> 8, w = seg & 255;
                    int row = w >> 2, u = w & 3;
                    uint32_t bo = (uint32_t)(row << 6) + (uint32_t)(u << 4);
                    dst = bbase + sp * FS_TILEA + (bo ^ ((bo >> 3) & 0x30u));
                    src = A[sp] + (size_t)row * 512 + (ch << 5) + (u << 3);
                } else {
                    int s2 = seg - 512;
                    int sp = s2 >> 9, w = s2 & 511;
                    int row = w >> 2, u = w & 3;
                    uint32_t bo = (uint32_t)(row << 6) + (uint32_t)(u << 4);
                    dst = bbase + 2 * FS_TILEA + sp * FS_TILEB
                        + (bo ^ ((bo >> 3) & 0x30u));
                    src = Bm[sp] + (size_t)row * 512 + (ch << 5) + (u << 3);
                }
                cp16(dst, src);
            }
            CP_COMMIT();
        };

        float hi[2][4][4], lo[2][4][4];
#pragma unroll
        for (int i = 0; i < 2; i++)
#pragma unroll
            for (int j = 0; j < 4; j++)
#pragma unroll
                for (int k = 0; k < 4; k++) { hi[i][j][k] = 0.0f; lo[i][j][k] = 0.0f; }

        issue(0, 0);

#pragma unroll 1
        for (int ch = 0; ch < 16; ++ch) {
            const int buf = ch & 1;
            if (ch < 15) { issue(ch + 1, buf ^ 1); CP_WAIT(1); }
            else         { CP_WAIT(0); }
            __syncthreads();

            const uint32_t stage = sb + (uint32_t)buf * FS_STAGE;

#pragma unroll
            for (int ks = 0; ks < 2; ++ks) {
                const uint32_t kb = (uint32_t)(ks * 32) + (uint32_t)((lane >> 4) << 4);

                uint32_t bq[2][2][4];
#pragma unroll
                for (int sp = 0; sp < 2; ++sp) {
                    const uint32_t Bt = stage + 2 * FS_TILEA + sp * FS_TILEB;
#pragma unroll
                    for (int nh = 0; nh < 2; ++nh) {
                        uint32_t row = (uint32_t)(wn * 32 + nh * 16 + (lane & 15));
                        uint32_t bo = (row << 6) + kb;
                        ldsm4(bq[sp][nh][0], bq[sp][nh][1], bq[sp][nh][2],
                              bq[sp][nh][3], Bt + (bo ^ ((bo >> 3) & 0x30u)));
                    }
                }
                uint32_t af[2][2][4];
#pragma unroll
                for (int sp = 0; sp < 2; ++sp) {
                    const uint32_t At = stage + sp * FS_TILEA;
#pragma unroll
                    for (int mi = 0; mi < 2; ++mi) {
                        uint32_t row = (uint32_t)(wm * 32 + mi * 16 + (lane & 15));
                        uint32_t bo = (row << 6) + kb;
                        ldsm4(af[sp][mi][0], af[sp][mi][1], af[sp][mi][2],
                              af[sp][mi][3], At + (bo ^ ((bo >> 3) & 0x30u)));
                    }
                }
#pragma unroll
                for (int mi = 0; mi < 2; ++mi)
#pragma unroll
                    for (int ni = 0; ni < 4; ++ni) {
                        uint32_t b00 = bq[0][ni >> 1][ni & 1];
                        uint32_t b01 = bq[0][ni >> 1][(ni & 1) + 2];
                        uint32_t b10 = bq[1][ni >> 1][ni & 1];
                        uint32_t b11 = bq[1][ni >> 1][(ni & 1) + 2];
                        mma16816(hi[mi][ni], af[0][mi], b00, b01);
                        mma16816(lo[mi][ni], af[0][mi], b10, b11);
                        mma16816(lo[mi][ni], af[1][mi], b00, b01);
                    }
            }
            __syncthreads();
        }

        const int tr = lane >> 2;
        const int tc = (lane & 3) << 1;
#pragma unroll
        for (int ni = 0; ni < 4; ++ni) {
            const int col = n0 + wn * 32 + ni * 8 + tc;
            const float bx = gh.bias[col];
            const float by = gh.bias[col + 1];
#pragma unroll
            for (int mi = 0; mi < 2; ++mi) {
                const int r0 = m0 + wm * 32 + mi * 16 + tr;
                float2 v0, v1;
                v0.x = fmaf(lo[mi][ni][0], RSCI, hi[mi][ni][0]) + bx;
                v0.y = fmaf(lo[mi][ni][1], RSCI, hi[mi][ni][1]) + by;
                v1.x = fmaf(lo[mi][ni][2], RSCI, hi[mi][ni][2]) + bx;
                v1.y = fmaf(lo[mi][ni][3], RSCI, hi[mi][ni][3]) + by;
                *(float2 *)(gh.c + (size_t)r0 * G3_ + col) = v0;
                *(float2 *)(gh.c + (size_t)(r0 + 8) * G3_ + col) = v1;
            }
        }
        return;
    }

    // ---------------- sampling ----------------
    const int b = blockIdx.x;
    float *sm = (float *)smem;          // [0..7] per-warp, [8..15] ent, [16..23] lsm,
    int *smi = (int *)smem;             // [24..31] idx, [32] m, [33] S, [34] tok

    float xx[8], gg[8], e8[8];
    const float *L = logits + (size_t)b * V_;
#pragma unroll
    for (int i = 0; i < 8; i++) {
        int v = tid + i * 256;
        xx[i] = L[v];
        uint32_t j = (uint32_t)b * 2048u + (uint32_t)v;
        uint32_t o0, o1;
        tf2x32(k0, k1, 0u, j, o0, o1);
        gg[i] = gumbelf(o0 ^ o1);
    }

    // block max
    float m = -INFINITY;
#pragma unroll
    for (int i = 0; i < 8; i++) m = fmaxf(m, xx[i]);
#pragma unroll
    for (int o = 16; o > 0; o >>= 1) m = fmaxf(m, __shfl_xor_sync(~0u, m, o));
    if (lane == 0) sm[wid] = m;
    __syncthreads();
    if (tid < 32) {
        float v = (lane < 8) ? sm[lane] : -INFINITY;
#pragma unroll
        for (int o = 4; o > 0; o >>= 1) v = fmaxf(v, __shfl_xor_sync(~0u, v, o));
        if (lane == 0) sm[32] = v;
    }
    __syncthreads();
    m = sm[32];

    // block sum of exp(x - m)
    float ss = 0.0f;
#pragma unroll
    for (int i = 0; i < 8; i++) { e8[i] = expf(xx[i] - m); ss += e8[i]; }
#pragma unroll
    for (int o = 16; o > 0; o >>= 1) ss += __shfl_xor_sync(~0u, ss, o);
    if (lane == 0) sm[wid] = ss;
    __syncthreads();
    if (tid < 32) {
        float v = (lane < 8) ? sm[lane] : 0.0f;
#pragma unroll
        for (int o = 4; o > 0; o >>= 1) v += __shfl_xor_sync(~0u, v, o);
        if (lane == 0) sm[33] = v;
    }
    __syncthreads();
    float Lg = logf(sm[33]);
    float inv = expf(-Lg);
    __syncthreads();   // everyone done reading sm[33] before reuse of sm[0..31]

    // per-element: lsm, entropy, gumbel argmax (first-index tie-break)
    float bv = -INFINITY, blsm = 0.0f, ent = 0.0f;
    int bi = 0x7FFFFFFF;
#pragma unroll
    for (int i = 0; i < 8; i++) {
        int v = tid + i * 256;
        float lsm = (xx[i] - m) - Lg;
        ent += (e8[i] * inv) * lsm;
        float val = lsm + gg[i];
        if (val > bv) { bv = val; bi = v; blsm = lsm; }
    }
#pragma unroll
    for (int o = 16; o > 0; o >>= 1) {
        float v2 = __shfl_xor_sync(~0u, bv, o);
        int   i2 = __shfl_xor_sync(~0u, bi, o);
        float l2 = __shfl_xor_sync(~0u, blsm, o);
        ent += __shfl_xor_sync(~0u, ent, o);
        if (v2 > bv || (v2 == bv && i2 < bi)) { bv = v2; bi = i2; blsm = l2; }
    }
    if (lane == 0) {
        sm[wid] = bv; sm[8 + wid] = ent; sm[16 + wid] = blsm; smi[24 + wid] = bi;
    }
    __syncthreads();
    if (tid < 32) {
        float v = (lane < 8) ? sm[lane] : -INFINITY;
        float e = (lane < 8) ? sm[8 + lane] : 0.0f;
        float l = (lane < 8) ? sm[16 + lane] : 0.0f;
        int   ix = (lane < 8) ? smi[24 + lane] : 0x7FFFFFFF;
#pragma unroll
        for (int o = 4; o > 0; o >>= 1) {
            float v2 = __shfl_xor_sync(~0u, v, o);
            int   i2 = __shfl_xor_sync(~0u, ix, o);
            float l2 = __shfl_xor_sync(~0u, l, o);
            e += __shfl_xor_sync(~0u, e, o);
            if (v2 > v || (v2 == v && i2 < ix)) { v = v2; ix = i2; l = l2; }
        }
        if (lane == 0) {
            oSeq[(size_t)b * T_ + t] = (float)ix;
            oLp [(size_t)b * T_ + t] = l;
            oEnt[(size_t)b * T_ + t] = -e;
            smi[34] = ix;
        }
    }
    __syncthreads();
    int tok = smi[34];

    for (int c = tid; c < 512; c += 256) {
        float v = etab[(size_t)tok * 512 + c];
        __half h0, h1;
        split2(v, h0, h1);
        size_t idx = (size_t)b * H_ + c;
        g_IA0[idx] = h0; g_IA1[idx] = h1;
    }
}

// ---------------------------------------------------------------------------
// GRU cell + LayerNorm; writes fp32 h AND its fp16x2 splits.
// ---------------------------------------------------------------------------
__global__ void __launch_bounds__(512) gru_ln(const float *__restrict__ ln_g,
                                              const float *__restrict__ ln_b) {
    const int b = blockIdx.x;
    const int j = threadIdx.x;
    const int wid = j >> 5;
    const int lane = j & 31;
    __shared__ float ws[16];
    __shared__ float bc[2];

    const float *gib = g_gi + (size_t)b * G3_;
    const float *ghb = g_gh + (size_t)b * G3_;
    float hv = g_h[(size_t)b * H_ + j];

    float r = sigx(gib[j] + ghb[j]);
    float z = sigx(gib[512 + j] + ghb[512 + j]);
    float n = tanhf(gib[1024 + j] + r * ghb[1024 + j]);
    float hn = (1.0f - z) * n + z * hv;

    float s = hn;
#pragma unroll
    for (int o = 16; o > 0; o >>= 1) s += __shfl_xor_sync(0xFFFFFFFFu, s, o);
    if (lane == 0) ws[wid] = s;
    __syncthreads();
    if (j < 32) {
        float v = (j < 16) ? ws[j] : 0.0f;
#pragma unroll
        for (int o = 8; o > 0; o >>= 1) v += __shfl_xor_sync(0xFFFFFFFFu, v, o);
        if (j == 0) bc[0] = v * (1.0f / 512.0f);
    }
    __syncthreads();
    float mu = bc[0];

    float d = hn - mu;
    s = d * d;
#pragma unroll
    for (int o = 16; o > 0; o >>= 1) s += __shfl_xor_sync(0xFFFFFFFFu, s, o);
    if (lane == 0) ws[wid] = s;
    __syncthreads();
    if (j < 32) {
        float v = (j < 16) ? ws[j] : 0.0f;
#pragma unroll
        for (int o = 8; o > 0; o >>= 1) v += __shfl_xor_sync(0xFFFFFFFFu, v, o);
        if (j == 0) bc[1] = v * (1.0f / 512.0f);
    }
    __syncthreads();
    float var = bc[1];

    float out = d * rsqrtf(var + 1e-5f) * ln_g[j] + ln_b[j];
    size_t idx = (size_t)b * H_ + j;
    g_h[idx] = out;
    __half h0, h1;
    split2(out, h0, h1);
    g_HA0[idx] = h0; g_HA1[idx] = h1;
}

// ---------------------------------------------------------------------------
// Init + weight splits
// ---------------------------------------------------------------------------
__global__ void __launch_bounds__(256) init_k(const float *__restrict__ emb,
                                              const float *__restrict__ sos) {
    int i = blockIdx.x * 256 + threadIdx.x;
    float x = emb[i];
    g_h[i] = x;
    __half h0, h1;
    split2(x, h0, h1);
    g_HA0[i] = h0; g_HA1[i] = h1;

    float y = sos[i & 511];
    split2(y, h0, h1);
    g_IA0[i] = h0; g_IA1[i] = h1;
}

__global__ void __launch_bounds__(256) splitw_k(const float *__restrict__ src,
                                                __half *d0, __half *d1, int n) {
    int i = blockIdx.x * 256 + threadIdx.x;
    if (i < n) {
        __half a, b;
        split2(src[i], a, b);
        d0[i] = a; d1[i] = b;
    }
}

// ---------------------------------------------------------------------------
// Host launcher (graph-capturable)
// ---------------------------------------------------------------------------
extern "C" void kernel_launch(void* const* d_in, const int* in_sizes, int n_in,
                              void* d_out, int out_size) {
    (void)in_sizes; (void)n_in; (void)out_size;
    const float* embedding = (const float*)d_in[0];
    const float* sos   = (const float*)d_in[2];
    const float* W_ih  = (const float*)d_in[3];
    const float* W_hh  = (const float*)d_in[4];
    const float* b_ih  = (const float*)d_in[5];
    const float* b_hh  = (const float*)d_in[6];
    const float* ln_g  = (const float*)d_in[7];
    const float* ln_b  = (const float*)d_in[8];
    const float* W_out = (const float*)d_in[9];
    const float* b_out = (const float*)d_in[10];
    const float* etab  = (const float*)d_in[11];

    float* out  = (float*)d_out;
    float* oSeq = out;
    float* oLp  = out + (size_t)B_ * T_;
    float* oEnt = out + (size_t)2 * B_ * T_;

    cudaFuncSetAttribute(gemm_f16x2, cudaFuncAttributeMaxDynamicSharedMemorySize,
                         SMEM_TOT);
    cudaFuncSetAttribute(fused_sample_gh,
                         cudaFuncAttributeMaxDynamicSharedMemorySize, FS_SMEM);

    float *pgi, *pgh, *plog;
    cudaGetSymbolAddress((void**)&pgi,  g_gi);
    cudaGetSymbolAddress((void**)&pgh,  g_gh);
    cudaGetSymbolAddress((void**)&plog, g_logits);

    __half *ia0, *ia1, *ha0, *ha1;
    __half *wih0, *wih1, *whh0, *whh1, *wo0, *wo1;
    cudaGetSymbolAddress((void**)&ia0, g_IA0); cudaGetSymbolAddress((void**)&ia1, g_IA1);
    cudaGetSymbolAddress((void**)&ha0, g_HA0); cudaGetSymbolAddress((void**)&ha1, g_HA1);
    cudaGetSymbolAddress((void**)&wih0, g_Wih0); cudaGetSymbolAddress((void**)&wih1, g_Wih1);
    cudaGetSymbolAddress((void**)&whh0, g_Whh0); cudaGetSymbolAddress((void**)&whh1, g_Whh1);
    cudaGetSymbolAddress((void**)&wo0, g_Wo0); cudaGetSymbolAddress((void**)&wo1, g_Wo1);

    splitw_k<<<(G3_ * H_ + 255) / 256, 256>>>(W_ih,  wih0, wih1, G3_ * H_);
    splitw_k<<<(G3_ * H_ + 255) / 256, 256>>>(W_hh,  whh0, whh1, G3_ * H_);
    splitw_k<<<(V_  * H_ + 255) / 256, 256>>>(W_out, wo0,  wo1,  V_ * H_);

    init_k<<<(B_ * H_) / 256, 256>>>(embedding, sos);

    GemmOps opIH = {ia0, ia1, wih0, wih1, b_ih, pgi};
    GemmOps opHH = {ha0, ha1, whh0, whh1, b_hh, pgh};
    GemmOps opO  = {ha0, ha1, wo0,  wo1,  b_out, plog};

    // prologue: gi(0) and gh(0) from (sos, embedding)
    dim3 gGate(G3_ / 128, B_ / 128, 2);
    gemm_f16x2<<<gGate, 512, SMEM_TOT>>>(opIH, opHH, G3_, 1);

    dim3 gOut(V_ / 128, B_ / 128, 1);
    dim3 gGi (G3_ / 128, B_ / 128, 1);

    for (int t = 0; t < T_; t++) {
        uint32_t fk0, fk1;
        tf2x32(0u, 42u, 0u, (uint32_t)t, fk0, fk1);   // fold_in(key(42), t)

        gru_ln<<<B_, 512>>>(ln_g, ln_b);
        gemm_f16x2<<<gOut, 512, SMEM_TOT>>>(opO, opO, V_, 0);

        // fused: sample(t)  ||  gh(t+1) = h'(t) @ Whh  (skip gh blocks at last t)
        int nblk = B_ + ((t < T_ - 1) ? (G3_ / 128) * (B_ / 64) : 0);
        fused_sample_gh<<<nblk, 256, FS_SMEM>>>(etab, fk0, fk1, t,
                                                oSeq, oLp, oEnt, plog, opHH);

        if (t < T_ - 1)
            gemm_f16x2<<<gGi, 512, SMEM_TOT>>>(opIH, opIH, G3_, 0);
    }
}

// round 11
// speedup vs baseline: 1.0474x; 1.0474x over previous
#include <cuda_runtime.h>
#include <cuda_fp16.h>
#include <cstdint>
#include <math.h>

#define B_  8192
#define H_  512
#define G3_ 1536
#define V_  2048
#define T_  24

// residual scale 2^11
#define RSC   2048.0f
#define RSCI  4.8828125e-4f

// ---------------------------------------------------------------------------
// Scratch (device globals: allocation-free)
// ---------------------------------------------------------------------------
__device__ float g_h[B_ * H_];
__device__ float g_gi[B_ * G3_];
__device__ float g_gh[B_ * G3_];
__device__ float g_logits[B_ * V_];
__device__ float g_gum[(size_t)B_ * V_];   // per-step Gumbel noise

// scaled fp16x2 splits: X = X0 + X1 * 2^-11
__device__ __half g_IA0[B_ * H_],  g_IA1[B_ * H_];
__device__ __half g_HA0[B_ * H_],  g_HA1[B_ * H_];
__device__ __half g_Wih0[G3_ * H_], g_Wih1[G3_ * H_];
__device__ __half g_Whh0[G3_ * H_], g_Whh1[G3_ * H_];
__device__ __half g_Wo0[V_ * H_],   g_Wo1[V_ * H_];

// ---------------------------------------------------------------------------
// Threefry-2x32 (exact JAX replica)
// ---------------------------------------------------------------------------
__host__ __device__ __forceinline__ uint32_t rotl32(uint32_t v, int r) {
    return (v << r) | (v >> (32 - r));
}

__host__ __device__ __forceinline__ void tf2x32(uint32_t k0, uint32_t k1,
                                                uint32_t c0, uint32_t c1,
                                                uint32_t &o0, uint32_t &o1) {
    const uint32_t k2 = k0 ^ k1 ^ 0x1BD11BDAu;
    uint32_t a = c0, b = c1;
    a += k0; b += k1;
#define TFR(r) { a += b; b = rotl32(b, r); b ^= a; }
    TFR(13) TFR(15) TFR(26) TFR(6)
    a += k1; b += k2 + 1u;
    TFR(17) TFR(29) TFR(16) TFR(24)
    a += k2; b += k0 + 2u;
    TFR(13) TFR(15) TFR(26) TFR(6)
    a += k0; b += k1 + 3u;
    TFR(17) TFR(29) TFR(16) TFR(24)
    a += k1; b += k2 + 4u;
    TFR(13) TFR(15) TFR(26) TFR(6)
    a += k2; b += k0 + 5u;
#undef TFR
    o0 = a; o1 = b;
}

__device__ __forceinline__ float gumbelf(uint32_t bits) {
    float f = __uint_as_float((bits >> 9) | 0x3F800000u) - 1.0f;
    float u = fmaxf(1.17549435082228751e-38f, f);
    return -logf(-logf(u));
}

__device__ __forceinline__ float sigx(float v) {
    return 0.5f * tanhf(0.5f * v) + 0.5f;
}

// scaled fp16x2 split: x ≈ h0 + h1 * 2^-11
__device__ __forceinline__ void split2(float x, __half &h0, __half &h1) {
    h0 = __float2half_rn(x);
    float r = x - __half2float(h0);
    h1 = __float2half_rn(r * RSC);
}

// ---------------------------------------------------------------------------
// mma.sync / ldmatrix / cp.async primitives
// ---------------------------------------------------------------------------
__device__ __forceinline__ uint32_t smem_u32(const void* p) {
    uint32_t a;
    asm("{ .reg .u64 t; cvta.to.shared.u64 t, %1; cvt.u32.u64 %0, t; }"
        : "=r"(a) : "l"(p));
    return a;
}

__device__ __forceinline__ void ldsm4(uint32_t &r0, uint32_t &r1,
                                      uint32_t &r2, uint32_t &r3, uint32_t addr) {
    asm volatile("ldmatrix.sync.aligned.m8n8.x4.shared.b16 {%0,%1,%2,%3}, [%4];"
                 : "=r"(r0), "=r"(r1), "=r"(r2), "=r"(r3) : "r"(addr));
}

__device__ __forceinline__ void mma16816(float *d, const uint32_t *a,
                                         uint32_t b0, uint32_t b1) {
    asm volatile(
        "mma.sync.aligned.m16n8k16.row.col.f32.f16.f16.f32 "
        "{%0,%1,%2,%3},{%4,%5,%6,%7},{%8,%9},{%0,%1,%2,%3};"
        : "+f"(d[0]), "+f"(d[1]), "+f"(d[2]), "+f"(d[3])
        : "r"(a[0]), "r"(a[1]), "r"(a[2]), "r"(a[3]), "r"(b0), "r"(b1));
}

__device__ __forceinline__ void cp16(uint32_t saddr, const void *g) {
    asm volatile("cp.async.cg.shared.global [%0], [%1], 16;"
                 :: "r"(saddr), "l"(g));
}
#define CP_COMMIT() asm volatile("cp.async.commit_group;" ::: "memory")
#define CP_WAIT(n)  asm volatile("cp.async.wait_group %0;" :: "n"(n) : "memory")

struct GemmOps { const __half *a0, *a1, *b0, *b1;
                 const float *bias; float *c; };

#define TILE_B   8192
#define STAGE_B  (4 * TILE_B)
#define SMEM_TOT (2 * STAGE_B)

// ---------------------------------------------------------------------------
// Shared GEMM tile body (128x128 CTA tile, 512 thr, 16 warps 4x4).
// Identical math to R9's gemm_f16x2 (proven at 14.42ms / rel_err 1.8e-7).
// ---------------------------------------------------------------------------
__device__ __forceinline__ void gemm_tile_body(const GemmOps &op, int m0, int n0,
                                               int N, char *smem) {
    const uint32_t sb = smem_u32(smem);
    const int tid = threadIdx.x;
    const int wid = tid >> 5;
    const int lane = tid & 31;
    const int wm = wid >> 2;
    const int wn = wid & 3;

    const __half *mats[4] = {
        op.a0 + (size_t)m0 * 512, op.a1 + (size_t)m0 * 512,
        op.b0 + (size_t)n0 * 512, op.b1 + (size_t)n0 * 512};

    auto issue = [&](int ch, int buf) {
        const uint32_t bbase = sb + (uint32_t)buf * STAGE_B;
#pragma unroll
        for (int s = 0; s < 4; ++s) {
            int seg = tid + s * 512;
            int m = seg >> 9;
            int w = seg & 511;
            int row = w >> 2;
            int u = w & 3;
            uint32_t bo = (uint32_t)(row << 6) + (uint32_t)(u << 4);
            uint32_t sw = bo ^ ((bo >> 3) & 0x30u);
            cp16(bbase + m * TILE_B + sw,
                 mats[m] + (size_t)row * 512 + (ch << 5) + (u << 3));
        }
        CP_COMMIT();
    };

    float hi[2][4][4], lo[2][4][4];
#pragma unroll
    for (int i = 0; i < 2; i++)
#pragma unroll
        for (int j = 0; j < 4; j++)
#pragma unroll
            for (int k = 0; k < 4; k++) { hi[i][j][k] = 0.0f; lo[i][j][k] = 0.0f; }

    issue(0, 0);

#pragma unroll 1
    for (int ch = 0; ch < 16; ++ch) {
        const int buf = ch & 1;
        if (ch < 15) { issue(ch + 1, buf ^ 1); CP_WAIT(1); }
        else         { CP_WAIT(0); }
        __syncthreads();

        const uint32_t stage = sb + (uint32_t)buf * STAGE_B;

#pragma unroll
        for (int ks = 0; ks < 2; ++ks) {
            const uint32_t kb = (uint32_t)(ks * 32) + (uint32_t)((lane >> 4) << 4);

            uint32_t bq[2][2][4];
#pragma unroll
            for (int sp = 0; sp < 2; ++sp) {
                const uint32_t Bt = stage + (2 + sp) * TILE_B;
#pragma unroll
                for (int nh = 0; nh < 2; ++nh) {
                    uint32_t row = (uint32_t)(wn * 32 + nh * 16 + (lane & 15));
                    uint32_t bo = (row << 6) + kb;
                    uint32_t sw = bo ^ ((bo >> 3) & 0x30u);
                    ldsm4(bq[sp][nh][0], bq[sp][nh][1], bq[sp][nh][2], bq[sp][nh][3],
                          Bt + sw);
                }
            }
            uint32_t af[2][2][4];
#pragma unroll
            for (int sp = 0; sp < 2; ++sp) {
                const uint32_t At = stage + sp * TILE_B;
#pragma unroll
                for (int mi = 0; mi < 2; ++mi) {
                    uint32_t row = (uint32_t)(wm * 32 + mi * 16 + (lane & 15));
                    uint32_t bo = (row << 6) + kb;
                    uint32_t sw = bo ^ ((bo >> 3) & 0x30u);
                    ldsm4(af[sp][mi][0], af[sp][mi][1], af[sp][mi][2], af[sp][mi][3],
                          At + sw);
                }
            }
#pragma unroll
            for (int mi = 0; mi < 2; ++mi)
#pragma unroll
                for (int ni = 0; ni < 4; ++ni) {
                    uint32_t b00 = bq[0][ni >> 1][ni & 1];
                    uint32_t b01 = bq[0][ni >> 1][(ni & 1) + 2];
                    uint32_t b10 = bq[1][ni >> 1][ni & 1];
                    uint32_t b11 = bq[1][ni >> 1][(ni & 1) + 2];
                    mma16816(hi[mi][ni], af[0][mi], b00, b01);
                    mma16816(lo[mi][ni], af[0][mi], b10, b11);
                    mma16816(lo[mi][ni], af[1][mi], b00, b01);
                }
        }
        __syncthreads();
    }

    const int tr = lane >> 2;
    const int tc = (lane & 3) << 1;
#pragma unroll
    for (int ni = 0; ni < 4; ++ni) {
        const int col = n0 + wn * 32 + ni * 8 + tc;
        const float bx = op.bias[col];
        const float by = op.bias[col + 1];
#pragma unroll
        for (int mi = 0; mi < 2; ++mi) {
            const int r0 = m0 + wm * 32 + mi * 16 + tr;
            float2 v0, v1;
            v0.x = fmaf(lo[mi][ni][0], RSCI, hi[mi][ni][0]) + bx;
            v0.y = fmaf(lo[mi][ni][1], RSCI, hi[mi][ni][1]) + by;
            v1.x = fmaf(lo[mi][ni][2], RSCI, hi[mi][ni][2]) + bx;
            v1.y = fmaf(lo[mi][ni][3], RSCI, hi[mi][ni][3]) + by;
            *(float2 *)(op.c + (size_t)r0 * N + col) = v0;
            *(float2 *)(op.c + (size_t)(r0 + 8) * N + col) = v1;
        }
    }
}

// ---------------------------------------------------------------------------
// Plain GEMM kernel (logits): 2-D grid (n-tiles, m-tiles)
// ---------------------------------------------------------------------------
__global__ void __launch_bounds__(512)
gemm_f16x2(GemmOps op, int N) {
    extern __shared__ char smem[];
    gemm_tile_body(op, blockIdx.y << 7, blockIdx.x << 7, N, smem);
}

// ---------------------------------------------------------------------------
// Gates GEMM + Gumbel generation, one launch (1-D grid):
//   blocks [0,768)      : gi tiles  (IA @ Wih^T)
//   blocks [768,1536)   : gh tiles  (HA @ Whh^T)
//   blocks [1536,3584)  : Gumbel(t) noise -> g_gum (pure ALU, backfills GEMM)
// ---------------------------------------------------------------------------
__global__ void __launch_bounds__(512)
gates_gum(GemmOps opIH, GemmOps opHH, uint32_t k0, uint32_t k1) {
    extern __shared__ char smem[];
    const int bid = blockIdx.x;
    if (bid < 1536) {
        const GemmOps &op = (bid < 768) ? opIH : opHH;
        const int local = (bid < 768) ? bid : bid - 768;
        gemm_tile_body(op, (local / 12) << 7, (local % 12) << 7, G3_, smem);
        return;
    }
    // Gumbel: 2048 blocks x 512 thr x 16 elements = 2^24
    const uint32_t gb = (uint32_t)(bid - 1536);
    const uint32_t base = gb * 8192u + (uint32_t)threadIdx.x;
#pragma unroll
    for (int k = 0; k < 16; ++k) {
        uint32_t j = base + (uint32_t)(k << 9);
        uint32_t o0, o1;
        tf2x32(k0, k1, 0u, j, o0, o1);
        g_gum[j] = gumbelf(o0 ^ o1);
    }
}

// ---------------------------------------------------------------------------
// Sampling: loads logits + precomputed gumbels; shuffle reductions;
// single-expf entropy; first-index tie-break argmax; embedding gather.
// ---------------------------------------------------------------------------
__global__ void __launch_bounds__(256) sample_k(
    const float *__restrict__ etab, int t,
    float *__restrict__ oSeq, float *__restrict__ oLp, float *__restrict__ oEnt) {
    const int b = blockIdx.x;
    const int tid = threadIdx.x;
    const int wid = tid >> 5;
    const int lane = tid & 31;

    __shared__ float sm[35];
    int *smi = (int *)sm;

    float xx[8], gg[8], e8[8];
    const float *L = g_logits + (size_t)b * V_;
    const float *G = g_gum + (size_t)b * V_;
#pragma unroll
    for (int i = 0; i < 8; i++) {
        int v = tid + i * 256;
        xx[i] = L[v];
        gg[i] = G[v];
    }

    // block max
    float m = -INFINITY;
#pragma unroll
    for (int i = 0; i < 8; i++) m = fmaxf(m, xx[i]);
#pragma unroll
    for (int o = 16; o > 0; o >>= 1) m = fmaxf(m, __shfl_xor_sync(~0u, m, o));
    if (lane == 0) sm[wid] = m;
    __syncthreads();
    if (tid < 32) {
        float v = (lane < 8) ? sm[lane] : -INFINITY;
#pragma unroll
        for (int o = 4; o > 0; o >>= 1) v = fmaxf(v, __shfl_xor_sync(~0u, v, o));
        if (lane == 0) sm[32] = v;
    }
    __syncthreads();
    m = sm[32];

    // block sum of exp(x - m)
    float ss = 0.0f;
#pragma unroll
    for (int i = 0; i < 8; i++) { e8[i] = expf(xx[i] - m); ss += e8[i]; }
#pragma unroll
    for (int o = 16; o > 0; o >>= 1) ss += __shfl_xor_sync(~0u, ss, o);
    if (lane == 0) sm[wid] = ss;
    __syncthreads();
    if (tid < 32) {
        float v = (lane < 8) ? sm[lane] : 0.0f;
#pragma unroll
        for (int o = 4; o > 0; o >>= 1) v += __shfl_xor_sync(~0u, v, o);
        if (lane == 0) sm[33] = v;
    }
    __syncthreads();
    float Lg = logf(sm[33]);
    float inv = expf(-Lg);
    __syncthreads();

    // per-element: lsm, entropy, gumbel argmax (first-index tie-break)
    float bv = -INFINITY, blsm = 0.0f, ent = 0.0f;
    int bi = 0x7FFFFFFF;
#pragma unroll
    for (int i = 0; i < 8; i++) {
        int v = tid + i * 256;
        float lsm = (xx[i] - m) - Lg;
        ent += (e8[i] * inv) * lsm;
        float val = lsm + gg[i];
        if (val > bv) { bv = val; bi = v; blsm = lsm; }
    }
#pragma unroll
    for (int o = 16; o > 0; o >>= 1) {
        float v2 = __shfl_xor_sync(~0u, bv, o);
        int   i2 = __shfl_xor_sync(~0u, bi, o);
        float l2 = __shfl_xor_sync(~0u, blsm, o);
        ent += __shfl_xor_sync(~0u, ent, o);
        if (v2 > bv || (v2 == bv && i2 < bi)) { bv = v2; bi = i2; blsm = l2; }
    }
    if (lane == 0) {
        sm[wid] = bv; sm[8 + wid] = ent; sm[16 + wid] = blsm; smi[24 + wid] = bi;
    }
    __syncthreads();
    if (tid < 32) {
        float v = (lane < 8) ? sm[lane] : -INFINITY;
        float e = (lane < 8) ? sm[8 + lane] : 0.0f;
        float l = (lane < 8) ? sm[16 + lane] : 0.0f;
        int   ix = (lane < 8) ? smi[24 + lane] : 0x7FFFFFFF;
#pragma unroll
        for (int o = 4; o > 0; o >>= 1) {
            float v2 = __shfl_xor_sync(~0u, v, o);
            int   i2 = __shfl_xor_sync(~0u, ix, o);
            float l2 = __shfl_xor_sync(~0u, l, o);
            e += __shfl_xor_sync(~0u, e, o);
            if (v2 > v || (v2 == v && i2 < ix)) { v = v2; ix = i2; l = l2; }
        }
        if (lane == 0) {
            oSeq[(size_t)b * T_ + t] = (float)ix;
            oLp [(size_t)b * T_ + t] = l;
            oEnt[(size_t)b * T_ + t] = -e;
            smi[34] = ix;
        }
    }
    __syncthreads();
    int tok = smi[34];

    for (int c = tid; c < 512; c += 256) {
        float v = etab[(size_t)tok * 512 + c];
        __half h0, h1;
        split2(v, h0, h1);
        size_t idx = (size_t)b * H_ + c;
        g_IA0[idx] = h0; g_IA1[idx] = h1;
    }
}

// ---------------------------------------------------------------------------
// GRU cell + LayerNorm; writes fp32 h AND its fp16x2 splits.
// ---------------------------------------------------------------------------
__global__ void __launch_bounds__(512) gru_ln(const float *__restrict__ ln_g,
                                              const float *__restrict__ ln_b) {
    const int b = blockIdx.x;
    const int j = threadIdx.x;
    const int wid = j >> 5;
    const int lane = j & 31;
    __shared__ float ws[16];
    __shared__ float bc[2];

    const float *gib = g_gi + (size_t)b * G3_;
    const float *ghb = g_gh + (size_t)b * G3_;
    float hv = g_h[(size_t)b * H_ + j];

    float r = sigx(gib[j] + ghb[j]);
    float z = sigx(gib[512 + j] + ghb[512 + j]);
    float n = tanhf(gib[1024 + j] + r * ghb[1024 + j]);
    float hn = (1.0f - z) * n + z * hv;

    float s = hn;
#pragma unroll
    for (int o = 16; o > 0; o >>= 1) s += __shfl_xor_sync(0xFFFFFFFFu, s, o);
    if (lane == 0) ws[wid] = s;
    __syncthreads();
    if (j < 32) {
        float v = (j < 16) ? ws[j] : 0.0f;
#pragma unroll
        for (int o = 8; o > 0; o >>= 1) v += __shfl_xor_sync(0xFFFFFFFFu, v, o);
        if (j == 0) bc[0] = v * (1.0f / 512.0f);
    }
    __syncthreads();
    float mu = bc[0];

    float d = hn - mu;
    s = d * d;
#pragma unroll
    for (int o = 16; o > 0; o >>= 1) s += __shfl_xor_sync(0xFFFFFFFFu, s, o);
    if (lane == 0) ws[wid] = s;
    __syncthreads();
    if (j < 32) {
        float v = (j < 16) ? ws[j] : 0.0f;
#pragma unroll
        for (int o = 8; o > 0; o >>= 1) v += __shfl_xor_sync(0xFFFFFFFFu, v, o);
        if (j == 0) bc[1] = v * (1.0f / 512.0f);
    }
    __syncthreads();
    float var = bc[1];

    float out = d * rsqrtf(var + 1e-5f) * ln_g[j] + ln_b[j];
    size_t idx = (size_t)b * H_ + j;
    g_h[idx] = out;
    __half h0, h1;
    split2(out, h0, h1);
    g_HA0[idx] = h0; g_HA1[idx] = h1;
}

// ---------------------------------------------------------------------------
// Init + weight splits
// ---------------------------------------------------------------------------
__global__ void __launch_bounds__(256) init_k(const float *__restrict__ emb,
                                              const float *__restrict__ sos) {
    int i = blockIdx.x * 256 + threadIdx.x;
    float x = emb[i];
    g_h[i] = x;
    __half h0, h1;
    split2(x, h0, h1);
    g_HA0[i] = h0; g_HA1[i] = h1;

    float y = sos[i & 511];
    split2(y, h0, h1);
    g_IA0[i] = h0; g_IA1[i] = h1;
}

__global__ void __launch_bounds__(256) splitw_k(const float *__restrict__ src,
                                                __half *d0, __half *d1, int n) {
    int i = blockIdx.x * 256 + threadIdx.x;
    if (i < n) {
        __half a, b;
        split2(src[i], a, b);
        d0[i] = a; d1[i] = b;
    }
}

// ---------------------------------------------------------------------------
// Host launcher (graph-capturable)
// ---------------------------------------------------------------------------
extern "C" void kernel_launch(void* const* d_in, const int* in_sizes, int n_in,
                              void* d_out, int out_size) {
    (void)in_sizes; (void)n_in; (void)out_size;
    const float* embedding = (const float*)d_in[0];
    const float* sos   = (const float*)d_in[2];
    const float* W_ih  = (const float*)d_in[3];
    const float* W_hh  = (const float*)d_in[4];
    const float* b_ih  = (const float*)d_in[5];
    const float* b_hh  = (const float*)d_in[6];
    const float* ln_g  = (const float*)d_in[7];
    const float* ln_b  = (const float*)d_in[8];
    const float* W_out = (const float*)d_in[9];
    const float* b_out = (const float*)d_in[10];
    const float* etab  = (const float*)d_in[11];

    float* out  = (float*)d_out;
    float* oSeq = out;
    float* oLp  = out + (size_t)B_ * T_;
    float* oEnt = out + (size_t)2 * B_ * T_;

    cudaFuncSetAttribute(gemm_f16x2, cudaFuncAttributeMaxDynamicSharedMemorySize,
                         SMEM_TOT);
    cudaFuncSetAttribute(gates_gum, cudaFuncAttributeMaxDynamicSharedMemorySize,
                         SMEM_TOT);

    float *pgi, *pgh, *plog;
    cudaGetSymbolAddress((void**)&pgi,  g_gi);
    cudaGetSymbolAddress((void**)&pgh,  g_gh);
    cudaGetSymbolAddress((void**)&plog, g_logits);

    __half *ia0, *ia1, *ha0, *ha1;
    __half *wih0, *wih1, *whh0, *whh1, *wo0, *wo1;
    cudaGetSymbolAddress((void**)&ia0, g_IA0); cudaGetSymbolAddress((void**)&ia1, g_IA1);
    cudaGetSymbolAddress((void**)&ha0, g_HA0); cudaGetSymbolAddress((void**)&ha1, g_HA1);
    cudaGetSymbolAddress((void**)&wih0, g_Wih0); cudaGetSymbolAddress((void**)&wih1, g_Wih1);
    cudaGetSymbolAddress((void**)&whh0, g_Whh0); cudaGetSymbolAddress((void**)&whh1, g_Whh1);
    cudaGetSymbolAddress((void**)&wo0, g_Wo0); cudaGetSymbolAddress((void**)&wo1, g_Wo1);

    splitw_k<<<(G3_ * H_ + 255) / 256, 256>>>(W_ih,  wih0, wih1, G3_ * H_);
    splitw_k<<<(G3_ * H_ + 255) / 256, 256>>>(W_hh,  whh0, whh1, G3_ * H_);
    splitw_k<<<(V_  * H_ + 255) / 256, 256>>>(W_out, wo0,  wo1,  V_ * H_);

    init_k<<<(B_ * H_) / 256, 256>>>(embedding, sos);

    GemmOps opIH = {ia0, ia1, wih0, wih1, b_ih, pgi};
    GemmOps opHH = {ha0, ha1, whh0, whh1, b_hh, pgh};
    GemmOps opO  = {ha0, ha1, wo0,  wo1,  b_out, plog};

    dim3 gOut(V_ / 128, B_ / 128);

    for (int t = 0; t < T_; t++) {
        uint32_t fk0, fk1;
        tf2x32(0u, 42u, 0u, (uint32_t)t, fk0, fk1);   // fold_in(key(42), t)

        // gates GEMM (gi+gh) with Gumbel(t) generation backfilled
        gates_gum<<<3584, 512, SMEM_TOT>>>(opIH, opHH, fk0, fk1);
        gru_ln<<<B_, 512>>>(ln_g, ln_b);
        gemm_f16x2<<<gOut, 512, SMEM_TOT>>>(opO, V_);
        sample_k<<<B_, 256>>>(etab, t, oSeq, oLp, oEnt);
    }
}